// round 15
// baseline (speedup 1.0000x reference)
#include <cuda_runtime.h>
#include <cuda_bf16.h>

// Problem constants
#define B_    64
#define N_    200000
#define V_    64          // 4^3 voxels
#define CLS_  40
#define BINS_ 65          // 64 real + 1 dummy (out-of-range) -> branchless SEL

// Histogram geometry (proven config): 16 chunks per batch, 256 threads.
// 200000/16 = 12500 points/block = 3125 groups of 4 points (exact).
#define CHUNKS_ 16
#define PTS_    (N_ / CHUNKS_)          // 12500
#define GRPS_   (PTS_ / 4)              // 3125
#define TPB_    256
#define FULL_ITERS_ (GRPS_ / TPB_)      // 12
#define TAIL_       (GRPS_ - FULL_ITERS_ * TPB_)  // 53

// Scratch (no cudaMalloc allowed): per-(batch,chunk) partial counts, written
// with plain stores each run (block owns its slot -> nothing to pre-zero,
// no atomics, no fences; the kernel boundary orders hist -> reduce).
__device__ int g_part[B_ * CHUNKS_][V_];

// Warp-aggregated shared-memory increment: lanes with equal bin are grouped
// via match.any; the group leader adds popc(group) once. The leader-only
// atomic is emitted as a PREDICATED red.shared (inline PTX) so ptxas cannot
// lower it to a BSSY/BSYNC divergence envelope (the R1 regression).
__device__ __forceinline__ void warp_agg_inc(int* slot, int bin, unsigned amask) {
    const unsigned mmask = __match_any_sync(amask, bin);
    const int cnt    = __popc(mmask);
    const int leader = __ffs(mmask) - 1;
    const int lane   = (int)(threadIdx.x & 31u);
    const unsigned saddr = (unsigned)__cvta_generic_to_shared(slot);
    const int is_leader = (lane == leader);
    asm volatile(
        "{\n\t"
        ".reg .pred p;\n\t"
        "setp.ne.s32 p, %0, 0;\n\t"
        "@p red.shared.add.u32 [%1], %2;\n\t"
        "}"
        :: "r"(is_leader), "r"(saddr), "r"(cnt) : "memory");
}

__global__ __launch_bounds__(TPB_) void hist_kernel(const float* __restrict__ x) {
    __shared__ int sh[BINS_];

    const int b     = blockIdx.y;
    const int chunk = blockIdx.x;
    const int tid   = threadIdx.x;

    if (tid < BINS_) sh[tid] = 0;
    __syncthreads();

    // This block's contiguous slice: 12500 points * 3 floats (48B groups).
    const float4* __restrict__ base = reinterpret_cast<const float4*>(
        x + ((size_t)b * N_ + (size_t)chunk * PTS_) * 3);

    auto do4 = [&](int g, unsigned amask) {
        // 4 points = 12 floats = 3 x LDG.128 (default cache policy)
        const float4 a = base[g * 3 + 0];
        const float4 c = base[g * 3 + 1];
        const float4 d = base[g * 3 + 2];
        const float px[4] = {a.x, a.w, c.z, d.y};
        const float py[4] = {a.y, c.x, c.w, d.z};
        const float pz[4] = {a.z, c.y, d.x, d.w};
#pragma unroll
        for (int p = 0; p < 4; p++) {
            const int i0 = __float2int_rd(px[p]);
            const int i1 = __float2int_rd(py[p]);
            const int i2 = __float2int_rd(pz[p]);
            // (i0+2)*16 + (i1+2)*4 + (i2+2) folded into +42
            int bin = i0 * 16 + i1 * 4 + i2 + 42;
            // in-range iff max(|x|,|y|,|z|) < 2; branchless SEL to dummy bin.
            // (strict bound drops only measure-zero boundary points and
            // guarantees bin in [0,63] for in-range points)
            const float m = fmaxf(fmaxf(fabsf(px[p]), fabsf(py[p])), fabsf(pz[p]));
            bin = (m < 2.0f) ? bin : 64;
            warp_agg_inc(&sh[bin], bin, amask);   // aggregated, predicated RED
        }
    };

    // unroll 2: proven best (unroll 4 regressed in A/B)
#pragma unroll 2
    for (int i = 0; i < FULL_ITERS_; i++) do4(i * TPB_ + tid, 0xFFFFFFFFu);
    if (tid < TAIL_) do4(FULL_ITERS_ * TPB_ + tid, __activemask());

    __syncthreads();

    // Publish this block's partial counts (plain stores; block owns the slot;
    // dummy bin 64 dropped). No fence needed: kernel boundary orders it.
    if (tid < V_) g_part[b * CHUNKS_ + chunk][tid] = sh[tid];
}

// One 256-thread block per batch row: parallel 16-way partial reduction,
// then warp-per-5-classes GEMV with shuffle reductions. (Proven best.)
__global__ __launch_bounds__(256) void out_kernel(const float* __restrict__ W,
                                                  const float* __restrict__ bias,
                                                  float* __restrict__ out) {
    __shared__ int   psum[4][V_];
    __shared__ float cf[V_];

    const int b   = blockIdx.x;
    const int tid = threadIdx.x;
    const int v   = tid & 63;        // voxel
    const int grp = tid >> 6;        // chunk group (0..3)

    // 256 threads each sum 4 of the 16 chunk partials -> 1024 parallel LDGs.
    int s = 0;
#pragma unroll
    for (int c = grp; c < CHUNKS_; c += 4) s += g_part[b * CHUNKS_ + c][v];
    psum[grp][v] = s;
    __syncthreads();

    if (tid < V_)
        cf[tid] = (float)(psum[0][tid] + psum[1][tid] + psum[2][tid] + psum[3][tid]);
    __syncthreads();

    // GEMV: 8 warps x 5 classes. Each lane owns voxels {lane, lane+32}.
    const int warp = tid >> 5;
    const int lane = tid & 31;
    const float c0 = cf[lane];
    const float c1 = cf[lane + 32];

    // total in-range count (same for all classes): one shuffle tree
    float t = c0 + c1;
#pragma unroll
    for (int o = 16; o > 0; o >>= 1) t += __shfl_xor_sync(0xFFFFFFFFu, t, o);
    const float inv = 1.0f / t;      // all lanes hold the full sum

#pragma unroll
    for (int k = 0; k < 5; k++) {
        const int cls = warp * 5 + k;
        const float* __restrict__ wr = W + cls * V_;
        float acc = c0 * wr[lane] + c1 * wr[lane + 32];   // coalesced
#pragma unroll
        for (int o = 16; o > 0; o >>= 1) acc += __shfl_xor_sync(0xFFFFFFFFu, acc, o);
        if (lane == 0) out[b * CLS_ + cls] = acc * inv + bias[cls];
    }
}

extern "C" void kernel_launch(void* const* d_in, const int* in_sizes, int n_in,
                              void* d_out, int out_size) {
    const float* x    = (const float*)d_in[0];   // [B, N, 3] f32
    const float* W    = (const float*)d_in[1];   // [CLASSES, V] f32
    const float* bias = (const float*)d_in[2];   // [CLASSES] f32
    float* out = (float*)d_out;                  // [B, CLASSES] f32

    hist_kernel<<<dim3(CHUNKS_, B_), TPB_>>>(x);
    out_kernel<<<B_, 256>>>(W, bias, out);
}

// round 16
// speedup vs baseline: 2.7140x; 2.7140x over previous
#include <cuda_runtime.h>
#include <cuda_bf16.h>

// Problem constants
#define B_    64
#define N_    200000
#define V_    64          // 4^3 voxels
#define CLS_  40
#define BINS_ 65          // 64 real + 1 dummy (out-of-range) -> branchless SEL

// Histogram geometry (proven config): 16 chunks per batch, 256 threads.
// 200000/16 = 12500 points/block = 3125 groups of 4 points (exact).
#define CHUNKS_ 16
#define PTS_    (N_ / CHUNKS_)          // 12500
#define GRPS_   (PTS_ / 4)              // 3125
#define TPB_    256
#define FULL_ITERS_ (GRPS_ / TPB_)      // 12
#define TAIL_       (GRPS_ - FULL_ITERS_ * TPB_)  // 53

// Scratch (no cudaMalloc allowed): per-(batch,chunk) partial counts, written
// with plain stores each run (block owns its slot -> nothing to pre-zero,
// no atomics, no fences; the kernel boundary orders hist -> reduce).
__device__ int g_part[B_ * CHUNKS_][V_];

__global__ __launch_bounds__(TPB_) void hist_kernel(const float* __restrict__ x) {
    __shared__ int sh[BINS_];

    const int b     = blockIdx.y;
    const int chunk = blockIdx.x;
    const int tid   = threadIdx.x;

    if (tid < BINS_) sh[tid] = 0;
    __syncthreads();

    // This block's contiguous slice: 12500 points * 3 floats (48B groups).
    const float4* __restrict__ base = reinterpret_cast<const float4*>(
        x + ((size_t)b * N_ + (size_t)chunk * PTS_) * 3);

    auto do4 = [&](int g) {
        // 4 points = 12 floats = 3 x LDG.128 (default cache policy)
        const float4 a = base[g * 3 + 0];
        const float4 c = base[g * 3 + 1];
        const float4 d = base[g * 3 + 2];
        const float px[4] = {a.x, a.w, c.z, d.y};
        const float py[4] = {a.y, c.x, c.w, d.z};
        const float pz[4] = {a.z, c.y, d.x, d.w};
#pragma unroll
        for (int p = 0; p < 4; p++) {
            const int i0 = __float2int_rd(px[p]);
            const int i1 = __float2int_rd(py[p]);
            const int i2 = __float2int_rd(pz[p]);
            // (i0+2)*16 + (i1+2)*4 + (i2+2) folded into +42
            int bin = i0 * 16 + i1 * 4 + i2 + 42;
            // in-range iff max(|x|,|y|,|z|) < 2; branchless SEL to dummy bin.
            // (strict bound drops only measure-zero boundary points and
            // guarantees bin in [0,63] for in-range points)
            const float m = fmaxf(fmaxf(fabsf(px[p]), fabsf(py[p])), fabsf(pz[p]));
            bin = (m < 2.0f) ? bin : 64;
            atomicAdd(&sh[bin], 1);          // unconditional ATOMS, no branch
        }
    };

    // unroll 2: proven best (unroll 4 regressed; warp-aggregation regressed 2.7x)
#pragma unroll 2
    for (int i = 0; i < FULL_ITERS_; i++) do4(i * TPB_ + tid);
    if (tid < TAIL_) do4(FULL_ITERS_ * TPB_ + tid);

    __syncthreads();

    // Publish this block's partial counts (plain stores; block owns the slot;
    // dummy bin 64 dropped). No fence needed: kernel boundary orders it.
    if (tid < V_) g_part[b * CHUNKS_ + chunk][tid] = sh[tid];
}

// One 256-thread block per batch row: parallel 16-way partial reduction,
// then warp-per-5-classes GEMV with shuffle reductions. (Proven best: the
// hoisted-W variant regressed.)
__global__ __launch_bounds__(256) void out_kernel(const float* __restrict__ W,
                                                  const float* __restrict__ bias,
                                                  float* __restrict__ out) {
    __shared__ int   psum[4][V_];
    __shared__ float cf[V_];

    const int b   = blockIdx.x;
    const int tid = threadIdx.x;
    const int v   = tid & 63;        // voxel
    const int grp = tid >> 6;        // chunk group (0..3)

    // 256 threads each sum 4 of the 16 chunk partials -> 1024 parallel LDGs.
    int s = 0;
#pragma unroll
    for (int c = grp; c < CHUNKS_; c += 4) s += g_part[b * CHUNKS_ + c][v];
    psum[grp][v] = s;
    __syncthreads();

    if (tid < V_)
        cf[tid] = (float)(psum[0][tid] + psum[1][tid] + psum[2][tid] + psum[3][tid]);
    __syncthreads();

    // GEMV: 8 warps x 5 classes. Each lane owns voxels {lane, lane+32}.
    const int warp = tid >> 5;
    const int lane = tid & 31;
    const float c0 = cf[lane];
    const float c1 = cf[lane + 32];

    // total in-range count (same for all classes): one shuffle tree
    float t = c0 + c1;
#pragma unroll
    for (int o = 16; o > 0; o >>= 1) t += __shfl_xor_sync(0xFFFFFFFFu, t, o);
    const float inv = 1.0f / t;      // all lanes hold the full sum

#pragma unroll
    for (int k = 0; k < 5; k++) {
        const int cls = warp * 5 + k;
        const float* __restrict__ wr = W + cls * V_;
        float acc = c0 * wr[lane] + c1 * wr[lane + 32];   // coalesced
#pragma unroll
        for (int o = 16; o > 0; o >>= 1) acc += __shfl_xor_sync(0xFFFFFFFFu, acc, o);
        if (lane == 0) out[b * CLS_ + cls] = acc * inv + bias[cls];
    }
}

extern "C" void kernel_launch(void* const* d_in, const int* in_sizes, int n_in,
                              void* d_out, int out_size) {
    const float* x    = (const float*)d_in[0];   // [B, N, 3] f32
    const float* W    = (const float*)d_in[1];   // [CLASSES, V] f32
    const float* bias = (const float*)d_in[2];   // [CLASSES] f32
    float* out = (float*)d_out;                  // [B, CLASSES] f32

    hist_kernel<<<dim3(CHUNKS_, B_), TPB_>>>(x);
    out_kernel<<<B_, 256>>>(W, bias, out);
}

// round 17
// speedup vs baseline: 2.7422x; 1.0104x over previous
#include <cuda_runtime.h>
#include <cuda_bf16.h>

// Problem constants
#define B_    64
#define N_    200000
#define V_    64          // 4^3 voxels
#define CLS_  40
#define BINS_ 65          // 64 real + 1 dummy (out-of-range) -> branchless SEL

// Histogram geometry (proven config): 16 chunks per batch, 256 threads.
// 200000/16 = 12500 points/block = 3125 groups of 4 points (exact).
#define CHUNKS_ 16
#define PTS_    (N_ / CHUNKS_)          // 12500
#define GRPS_   (PTS_ / 4)              // 3125
#define TPB_    256
#define FULL_ITERS_ (GRPS_ / TPB_)      // 12
#define TAIL_       (GRPS_ - FULL_ITERS_ * TPB_)  // 53

// Scratch (no cudaMalloc allowed): per-(batch,chunk) partial counts, written
// with plain stores each run (block owns its slot -> nothing to pre-zero,
// no atomics, no fences; the grid dependency orders hist -> reduce).
__device__ int g_part[B_ * CHUNKS_][V_];

__global__ __launch_bounds__(TPB_) void hist_kernel(const float* __restrict__ x) {
    __shared__ int sh[BINS_];

    const int b     = blockIdx.y;
    const int chunk = blockIdx.x;
    const int tid   = threadIdx.x;

    if (tid < BINS_) sh[tid] = 0;
    __syncthreads();

    // This block's contiguous slice: 12500 points * 3 floats (48B groups).
    const float4* __restrict__ base = reinterpret_cast<const float4*>(
        x + ((size_t)b * N_ + (size_t)chunk * PTS_) * 3);

    auto do4 = [&](int g) {
        // 4 points = 12 floats = 3 x LDG.128 (default cache policy)
        const float4 a = base[g * 3 + 0];
        const float4 c = base[g * 3 + 1];
        const float4 d = base[g * 3 + 2];
        const float px[4] = {a.x, a.w, c.z, d.y};
        const float py[4] = {a.y, c.x, c.w, d.z};
        const float pz[4] = {a.z, c.y, d.x, d.w};
#pragma unroll
        for (int p = 0; p < 4; p++) {
            const int i0 = __float2int_rd(px[p]);
            const int i1 = __float2int_rd(py[p]);
            const int i2 = __float2int_rd(pz[p]);
            // (i0+2)*16 + (i1+2)*4 + (i2+2) folded into +42
            int bin = i0 * 16 + i1 * 4 + i2 + 42;
            // in-range iff max(|x|,|y|,|z|) < 2; branchless SEL to dummy bin.
            // (strict bound drops only measure-zero boundary points and
            // guarantees bin in [0,63] for in-range points)
            const float m = fmaxf(fmaxf(fabsf(px[p]), fabsf(py[p])), fabsf(pz[p]));
            bin = (m < 2.0f) ? bin : 64;
            atomicAdd(&sh[bin], 1);          // unconditional ATOMS, no branch
        }
    };

    // unroll 2: proven best (unroll 4 regressed; warp-aggregation regressed 2.7x)
#pragma unroll 2
    for (int i = 0; i < FULL_ITERS_; i++) do4(i * TPB_ + tid);
    if (tid < TAIL_) do4(FULL_ITERS_ * TPB_ + tid);

    __syncthreads();

    // Publish this block's partial counts (plain stores; block owns the slot;
    // dummy bin 64 dropped).
    if (tid < V_) g_part[b * CHUNKS_ + chunk][tid] = sh[tid];
}

// One 256-thread block per batch row, launched with PDL: W/bias prefetch runs
// BEFORE cudaGridDependencySynchronize() so it overlaps the hist kernel's
// tail; g_part reads strictly after the dependency sync.
__global__ __launch_bounds__(256) void out_kernel(const float* __restrict__ W,
                                                  const float* __restrict__ bias,
                                                  float* __restrict__ out) {
    __shared__ int   psum[4][V_];
    __shared__ float cf[V_];

    const int b    = blockIdx.x;
    const int tid  = threadIdx.x;
    const int v    = tid & 63;       // voxel
    const int grp  = tid >> 6;       // chunk group (0..3)
    const int warp = tid >> 5;       // 8 warps x 5 classes
    const int lane = tid & 31;

    // ---- Independent prefetch: overlaps the still-running hist kernel ----
    float w0[5], w1[5], bv[5];
#pragma unroll
    for (int k = 0; k < 5; k++) {
        const int cls = warp * 5 + k;
        w0[k] = W[cls * V_ + lane];          // coalesced row reads
        w1[k] = W[cls * V_ + lane + 32];
        bv[k] = bias[cls];
    }

    // ---- Wait for hist completion before touching g_part ----
    cudaGridDependencySynchronize();

    int s = 0;
#pragma unroll
    for (int c = grp; c < CHUNKS_; c += 4) s += g_part[b * CHUNKS_ + c][v];
    psum[grp][v] = s;
    __syncthreads();

    if (tid < V_)
        cf[tid] = (float)(psum[0][tid] + psum[1][tid] + psum[2][tid] + psum[3][tid]);
    __syncthreads();

    // Each lane owns voxels {lane, lane+32}.
    const float c0 = cf[lane];
    const float c1 = cf[lane + 32];

    // total in-range count (same for all classes): one shuffle tree
    float t = c0 + c1;
#pragma unroll
    for (int o = 16; o > 0; o >>= 1) t += __shfl_xor_sync(0xFFFFFFFFu, t, o);
    const float inv = 1.0f / t;      // all lanes hold the full sum

#pragma unroll
    for (int k = 0; k < 5; k++) {
        float acc = c0 * w0[k] + c1 * w1[k];
#pragma unroll
        for (int o = 16; o > 0; o >>= 1) acc += __shfl_xor_sync(0xFFFFFFFFu, acc, o);
        if (lane == 0) out[b * CLS_ + warp * 5 + k] = acc * inv + bv[k];
    }
}

extern "C" void kernel_launch(void* const* d_in, const int* in_sizes, int n_in,
                              void* d_out, int out_size) {
    const float* x    = (const float*)d_in[0];   // [B, N, 3] f32
    const float* W    = (const float*)d_in[1];   // [CLASSES, V] f32
    const float* bias = (const float*)d_in[2];   // [CLASSES] f32
    float* out = (float*)d_out;                  // [B, CLASSES] f32

    hist_kernel<<<dim3(CHUNKS_, B_), TPB_>>>(x);

    // PDL launch: allow out_kernel to begin (prefetch phase) while hist
    // drains; the device-side grid sync provides the g_part ordering.
    cudaLaunchConfig_t cfg = {};
    cfg.gridDim  = dim3(B_);
    cfg.blockDim = dim3(256);
    cfg.dynamicSmemBytes = 0;
    cfg.stream = 0;
    cudaLaunchAttribute attr[1];
    attr[0].id = cudaLaunchAttributeProgrammaticStreamSerialization;
    attr[0].val.programmaticStreamSerializationAllowed = 1;
    cfg.attrs = attr;
    cfg.numAttrs = 1;
    cudaLaunchKernelEx(&cfg, out_kernel, W, bias, out);
}